// round 1
// baseline (speedup 1.0000x reference)
#include <cuda_runtime.h>
#include <math.h>

// ============================================================================
// FamNet pipeline, fp32 direct implementation.
// B=2 images (3,384,384), P=3 exemplar boxes.
// Backbone: conv7x7s2 -> conv3x3s2 -> conv3x3s2 (f3: 512x48x48) -> conv3x3s2 (f4: 1024x24x24)
// Features: per (b, level, scale) patch-correlation -> sims (2,3,6,48,48)
// Regressor: conv7(196) -> up2x -> conv5(128) -> up2x -> conv3(64) -> up2x
//            -> conv1(32) -> conv1(1) -> max over P -> (2,1,384,384)
// ============================================================================

#define NB 2
#define NP 3

// ---------------- device scratch (no allocations allowed) -------------------
__device__ float g_x1[2 * 64 * 192 * 192];
__device__ float g_x2[2 * 256 * 96 * 96];
__device__ float g_f3[2 * 512 * 48 * 48];
__device__ float g_f4[2 * 1024 * 24 * 24];
__device__ float g_patches[3 * 1024 * 24 * 24];   // stride-24 layout
__device__ float g_pf[3 * 1024 * 32 * 32];        // stride-32 layout
__device__ float g_simtmp[3 * 48 * 48];
__device__ float g_sims[2 * 3 * 6 * 48 * 48];
__device__ float g_r1[6 * 196 * 48 * 48];
__device__ float g_u1[6 * 196 * 96 * 96];
__device__ float g_r2[6 * 128 * 96 * 96];
__device__ float g_u2[6 * 128 * 192 * 192];
__device__ float g_r3[6 * 64 * 192 * 192];
__device__ float g_u3[6 * 64 * 384 * 384];
__device__ float g_r4[6 * 32 * 384 * 384];
__device__ float g_r5[6 * 384 * 384];

// ---------------- box / scale metadata (computed on device) -----------------
__device__ int g_tl[2][2][3][2];     // [b][level][p][{top,left}]
__device__ int g_crop[2][2][3][2];   // [b][level][p][{h,w}]
__device__ int g_PH[2][2], g_PW[2][2];
__device__ int g_PHs[2][2][3], g_PWs[2][2][3];

__global__ void meta_kernel(const float* __restrict__ tlbrs) {
    if (threadIdx.x != 0 || blockIdx.x != 0) return;
    const double scales[3] = {1.0, 0.9, 1.1};
    for (int b = 0; b < NB; b++) {
        for (int L = 0; L < 2; L++) {
            int F = (L == 0) ? 48 : 24;
            float inv = (float)F / 384.0f;  // 1/8 or 1/16, exact in binary
            int maxh = 0, maxw = 0;
            for (int p = 0; p < NP; p++) {
                const float* v = tlbrs + (b * NP + p) * 4;
                float sct = v[0] * inv, scl = v[1] * inv;
                float scb = v[2] * inv, scr = v[3] * inv;
                int top = (int)floorf(sct); if (top < 0) top = 0;
                int left = (int)floorf(scl); if (left < 0) left = 0;
                int bot = (int)ceilf(scb) + 1; if (bot > F) bot = F;
                int right = (int)ceilf(scr) + 1; if (right > F) right = F;
                g_tl[b][L][p][0] = top;  g_tl[b][L][p][1] = left;
                g_crop[b][L][p][0] = bot - top;  g_crop[b][L][p][1] = right - left;
                if (bot - top > maxh) maxh = bot - top;
                if (right - left > maxw) maxw = right - left;
            }
            g_PH[b][L] = maxh; g_PW[b][L] = maxw;
            for (int s = 0; s < 3; s++) {
                int ph = (int)ceil((double)maxh * scales[s]);
                int pw = (int)ceil((double)maxw * scales[s]);
                if (ph < 1) ph = maxh;
                if (pw < 1) pw = maxw;
                g_PHs[b][L][s] = ph; g_PWs[b][L][s] = pw;
            }
        }
    }
}

// ---------------- generic direct conv (+bias, +relu) ------------------------
template <int K>
__global__ void conv2d_k(const float* __restrict__ in, const float* __restrict__ wt,
                         const float* __restrict__ bias, float* __restrict__ out,
                         int N, int Cin, int Hin, int Win,
                         int Cout, int Hout, int Wout,
                         int stride, int pad, int relu) {
    int idx = blockIdx.x * blockDim.x + threadIdx.x;
    int total = N * Cout * Hout * Wout;
    if (idx >= total) return;
    int ox = idx % Wout;
    int t = idx / Wout;
    int oy = t % Hout; t /= Hout;
    int co = t % Cout;
    int n = t / Cout;

    float acc = bias ? bias[co] : 0.0f;
    const float* wb = wt + (size_t)co * Cin * K * K;
    const float* ib = in + (size_t)n * Cin * Hin * Win;
    int y0 = oy * stride - pad;
    int x0 = ox * stride - pad;

    for (int ci = 0; ci < Cin; ci++) {
        const float* ip = ib + (size_t)ci * Hin * Win;
        const float* wp = wb + ci * K * K;
#pragma unroll
        for (int kh = 0; kh < K; kh++) {
            int iy = y0 + kh;
            if ((unsigned)iy >= (unsigned)Hin) continue;
            const float* row = ip + (size_t)iy * Win;
#pragma unroll
            for (int kw = 0; kw < K; kw++) {
                int ix = x0 + kw;
                if ((unsigned)ix < (unsigned)Win)
                    acc = fmaf(__ldg(row + ix), wp[kh * K + kw], acc);
            }
        }
    }
    if (relu) acc = fmaxf(acc, 0.0f);
    out[idx] = acc;
}

// ---------------- half-pixel bilinear patch extraction ----------------------
// fm: (C,F,F) for one batch/level. Crop [top:top+h, left:left+w] -> (PH,PW).
__global__ void extract_patches_kernel(const float* __restrict__ fm, float* __restrict__ patches,
                                       int C, int F, int b, int L) {
    int idx = blockIdx.x * blockDim.x + threadIdx.x;
    int total = NP * C * 24 * 24;
    if (idx >= total) return;
    int ox = idx % 24;
    int oy = (idx / 24) % 24;
    int c = (idx / 576) % C;
    int p = idx / (576 * C);
    int PH = g_PH[b][L], PW = g_PW[b][L];
    if (oy >= PH || ox >= PW) return;
    int top = g_tl[b][L][p][0], left = g_tl[b][L][p][1];
    int h = g_crop[b][L][p][0], w = g_crop[b][L][p][1];

    float sy = ((float)oy + 0.5f) * ((float)h / (float)PH) - 0.5f;
    if (sy < 0.0f) sy = 0.0f;
    float sx = ((float)ox + 0.5f) * ((float)w / (float)PW) - 0.5f;
    if (sx < 0.0f) sx = 0.0f;
    int y0 = (int)sy; float ty = sy - (float)y0;
    int x0 = (int)sx; float tx = sx - (float)x0;
    if (y0 > h - 1) { y0 = h - 1; ty = 0.0f; }
    if (x0 > w - 1) { x0 = w - 1; tx = 0.0f; }
    int y1 = min(y0 + 1, h - 1);
    int x1 = min(x0 + 1, w - 1);

    const float* base = fm + ((size_t)c * F + top) * F + left;
    float v00 = base[y0 * F + x0], v01 = base[y0 * F + x1];
    float v10 = base[y1 * F + x0], v11 = base[y1 * F + x1];
    float val = v00 * (1.0f - ty) * (1.0f - tx) + v01 * (1.0f - ty) * tx
              + v10 * ty * (1.0f - tx) + v11 * ty * tx;
    patches[((size_t)(p * C + c) * 24 + oy) * 24 + ox] = val;
}

// patches (PH,PW, stride 24) -> pf (PHs,PWs, stride 32), half-pixel bilinear
__global__ void resize_patches_kernel(const float* __restrict__ patches, float* __restrict__ pf,
                                      int C, int b, int L, int s) {
    int idx = blockIdx.x * blockDim.x + threadIdx.x;
    int total = NP * C * 32 * 32;
    if (idx >= total) return;
    int ox = idx % 32;
    int oy = (idx / 32) % 32;
    int c = (idx / 1024) % C;
    int p = idx / (1024 * C);
    int PHs = g_PHs[b][L][s], PWs = g_PWs[b][L][s];
    if (oy >= PHs || ox >= PWs) return;
    int PH = g_PH[b][L], PW = g_PW[b][L];

    float sy = ((float)oy + 0.5f) * ((float)PH / (float)PHs) - 0.5f;
    if (sy < 0.0f) sy = 0.0f;
    float sx = ((float)ox + 0.5f) * ((float)PW / (float)PWs) - 0.5f;
    if (sx < 0.0f) sx = 0.0f;
    int y0 = (int)sy; float ty = sy - (float)y0;
    int x0 = (int)sx; float tx = sx - (float)x0;
    if (y0 > PH - 1) { y0 = PH - 1; ty = 0.0f; }
    if (x0 > PW - 1) { x0 = PW - 1; tx = 0.0f; }
    int y1 = min(y0 + 1, PH - 1);
    int x1 = min(x0 + 1, PW - 1);

    const float* base = patches + (size_t)(p * C + c) * 576;
    float v00 = base[y0 * 24 + x0], v01 = base[y0 * 24 + x1];
    float v10 = base[y1 * 24 + x0], v11 = base[y1 * 24 + x1];
    float val = v00 * (1.0f - ty) * (1.0f - tx) + v01 * (1.0f - ty) * tx
              + v10 * ty * (1.0f - tx) + v11 * ty * tx;
    pf[((size_t)(p * C + c) * 32 + oy) * 32 + ox] = val;
}

// ---------------- correlation: one block per output pixel -------------------
// sim[p,y,x] = sum_{c,i,j} fm[c, y+i-PHs/2, x+j-PWs/2] * pf[p,c,i,j]
__global__ void sim_kernel(const float* __restrict__ fm, const float* __restrict__ pf,
                           float* __restrict__ simtmp, int C, int F, int b, int L, int s) {
    int blk = blockIdx.x;
    int p = blk / (F * F);
    int rem = blk % (F * F);
    int y = rem / F, x = rem % F;
    int PHs = g_PHs[b][L][s], PWs = g_PWs[b][L][s];
    int padT = PHs >> 1, padL = PWs >> 1;
    int phw = PHs * PWs;
    int tid = threadIdx.x;

    int fmo[3], pfo[3];
#pragma unroll
    for (int k = 0; k < 3; k++) {
        fmo[k] = -1; pfo[k] = 0;
        int ij = tid + k * 256;
        if (ij < phw) {
            int i = ij / PWs, j = ij - i * PWs;
            int iy = y + i - padT, ix = x + j - padL;
            if (iy >= 0 && iy < F && ix >= 0 && ix < F) {
                fmo[k] = iy * F + ix;
                pfo[k] = i * 32 + j;
            }
        }
    }
    float acc = 0.0f;
    const float* pfb = pf + (size_t)p * C * 1024;
    for (int c = 0; c < C; c++) {
        const float* fmc = fm + (size_t)c * F * F;
        const float* pfc = pfb + (size_t)c * 1024;
#pragma unroll
        for (int k = 0; k < 3; k++)
            if (fmo[k] >= 0) acc = fmaf(__ldg(fmc + fmo[k]), pfc[pfo[k]], acc);
    }
    __shared__ float red[256];
    red[tid] = acc;
    __syncthreads();
    for (int off = 128; off > 0; off >>= 1) {
        if (tid < off) red[tid] += red[tid + off];
        __syncthreads();
    }
    if (tid == 0) simtmp[blk] = red[0];
}

// simtmp (P,F,F) -> sims[b,:,ch,48,48], half-pixel bilinear
__global__ void sim_resize_kernel(const float* __restrict__ simtmp, float* __restrict__ sims,
                                  int F, int b, int ch) {
    int idx = blockIdx.x * blockDim.x + threadIdx.x;
    if (idx >= NP * 48 * 48) return;
    int x = idx % 48;
    int y = (idx / 48) % 48;
    int p = idx / 2304;

    float sy = ((float)y + 0.5f) * ((float)F / 48.0f) - 0.5f;
    if (sy < 0.0f) sy = 0.0f;
    float sx = ((float)x + 0.5f) * ((float)F / 48.0f) - 0.5f;
    if (sx < 0.0f) sx = 0.0f;
    int y0 = (int)sy; float ty = sy - (float)y0;
    int x0 = (int)sx; float tx = sx - (float)x0;
    if (y0 > F - 1) { y0 = F - 1; ty = 0.0f; }
    if (x0 > F - 1) { x0 = F - 1; tx = 0.0f; }
    int y1 = min(y0 + 1, F - 1);
    int x1 = min(x0 + 1, F - 1);

    const float* base = simtmp + (size_t)p * F * F;
    float v00 = base[y0 * F + x0], v01 = base[y0 * F + x1];
    float v10 = base[y1 * F + x0], v11 = base[y1 * F + x1];
    float val = v00 * (1.0f - ty) * (1.0f - tx) + v01 * (1.0f - ty) * tx
              + v10 * ty * (1.0f - tx) + v11 * ty * tx;
    sims[((size_t)(b * NP + p) * 6 + ch) * 2304 + y * 48 + x] = val;
}

// ---------------- align-corners 2x bilinear upsample ------------------------
__global__ void upsample_kernel(const float* __restrict__ in, float* __restrict__ out,
                                int NC, int h, int w) {
    int H = 2 * h, W = 2 * w;
    int idx = blockIdx.x * blockDim.x + threadIdx.x;
    int total = NC * H * W;
    if (idx >= total) return;
    int ox = idx % W;
    int oy = (idx / W) % H;
    int nc = idx / (H * W);

    float stepy = (float)(h - 1) / (float)(H - 1);
    float stepx = (float)(w - 1) / (float)(W - 1);
    float py = (float)oy * stepy;
    float px = (float)ox * stepx;
    int y0 = (int)py; float ty = py - (float)y0;
    int x0 = (int)px; float tx = px - (float)x0;
    if (y0 > h - 1) { y0 = h - 1; ty = 0.0f; }
    if (x0 > w - 1) { x0 = w - 1; tx = 0.0f; }
    int y1 = min(y0 + 1, h - 1);
    int x1 = min(x0 + 1, w - 1);

    const float* ib = in + (size_t)nc * h * w;
    float v00 = ib[y0 * w + x0], v01 = ib[y0 * w + x1];
    float v10 = ib[y1 * w + x0], v11 = ib[y1 * w + x1];
    out[idx] = v00 * (1.0f - ty) * (1.0f - tx) + v01 * (1.0f - ty) * tx
             + v10 * ty * (1.0f - tx) + v11 * ty * tx;
}

// ---------------- final max over P ------------------------------------------
__global__ void maxp_kernel(const float* __restrict__ r5, float* __restrict__ out) {
    int idx = blockIdx.x * blockDim.x + threadIdx.x;
    const int HW = 384 * 384;
    if (idx >= NB * HW) return;
    int b = idx / HW;
    int r = idx % HW;
    float m = r5[(size_t)(b * NP + 0) * HW + r];
    m = fmaxf(m, r5[(size_t)(b * NP + 1) * HW + r]);
    m = fmaxf(m, r5[(size_t)(b * NP + 2) * HW + r]);
    out[idx] = m;
}

// ---------------- host-side launch helpers ----------------------------------
static inline int cdiv(int a, int b) { return (a + b - 1) / b; }

static void run_conv(const float* in, const float* w, const float* b, float* out,
                     int N, int Cin, int Hin, int Win, int Cout,
                     int K, int stride, int pad, bool relu) {
    int Hout = (Hin + 2 * pad - K) / stride + 1;
    int Wout = (Win + 2 * pad - K) / stride + 1;
    int total = N * Cout * Hout * Wout;
    int gs = cdiv(total, 256);
    int rl = relu ? 1 : 0;
    switch (K) {
        case 1: conv2d_k<1><<<gs, 256>>>(in, w, b, out, N, Cin, Hin, Win, Cout, Hout, Wout, stride, pad, rl); break;
        case 3: conv2d_k<3><<<gs, 256>>>(in, w, b, out, N, Cin, Hin, Win, Cout, Hout, Wout, stride, pad, rl); break;
        case 5: conv2d_k<5><<<gs, 256>>>(in, w, b, out, N, Cin, Hin, Win, Cout, Hout, Wout, stride, pad, rl); break;
        case 7: conv2d_k<7><<<gs, 256>>>(in, w, b, out, N, Cin, Hin, Win, Cout, Hout, Wout, stride, pad, rl); break;
    }
}

extern "C" void kernel_launch(void* const* d_in, const int* in_sizes, int n_in,
                              void* d_out, int out_size) {
    const float* images = (const float*)d_in[0];
    const float* tlbrs  = (const float*)d_in[1];
    const float* fw1 = (const float*)d_in[2];
    const float* fw2 = (const float*)d_in[3];
    const float* fw3 = (const float*)d_in[4];
    const float* fw4 = (const float*)d_in[5];
    const float* rw1 = (const float*)d_in[6];
    const float* rb1 = (const float*)d_in[7];
    const float* rw2 = (const float*)d_in[8];
    const float* rb2 = (const float*)d_in[9];
    const float* rw3 = (const float*)d_in[10];
    const float* rb3 = (const float*)d_in[11];
    const float* rw4 = (const float*)d_in[12];
    const float* rb4 = (const float*)d_in[13];
    const float* rw5 = (const float*)d_in[14];
    const float* rb5 = (const float*)d_in[15];
    float* out = (float*)d_out;

    float *x1, *x2, *f3, *f4, *patches, *pf, *simtmp, *sims;
    float *r1, *u1, *r2, *u2, *r3, *u3, *r4, *r5;
    cudaGetSymbolAddress((void**)&x1, g_x1);
    cudaGetSymbolAddress((void**)&x2, g_x2);
    cudaGetSymbolAddress((void**)&f3, g_f3);
    cudaGetSymbolAddress((void**)&f4, g_f4);
    cudaGetSymbolAddress((void**)&patches, g_patches);
    cudaGetSymbolAddress((void**)&pf, g_pf);
    cudaGetSymbolAddress((void**)&simtmp, g_simtmp);
    cudaGetSymbolAddress((void**)&sims, g_sims);
    cudaGetSymbolAddress((void**)&r1, g_r1);
    cudaGetSymbolAddress((void**)&u1, g_u1);
    cudaGetSymbolAddress((void**)&r2, g_r2);
    cudaGetSymbolAddress((void**)&u2, g_u2);
    cudaGetSymbolAddress((void**)&r3, g_r3);
    cudaGetSymbolAddress((void**)&u3, g_u3);
    cudaGetSymbolAddress((void**)&r4, g_r4);
    cudaGetSymbolAddress((void**)&r5, g_r5);

    // box metadata
    meta_kernel<<<1, 1>>>(tlbrs);

    // backbone
    run_conv(images, fw1, nullptr, x1, 2, 3, 384, 384, 64, 7, 2, 3, true);
    run_conv(x1, fw2, nullptr, x2, 2, 64, 192, 192, 256, 3, 2, 1, true);
    run_conv(x2, fw3, nullptr, f3, 2, 256, 96, 96, 512, 3, 2, 1, true);
    run_conv(f3, fw4, nullptr, f4, 2, 512, 48, 48, 1024, 3, 2, 1, true);

    // similarity features
    for (int b = 0; b < NB; b++) {
        for (int L = 0; L < 2; L++) {
            int C = L ? 1024 : 512;
            int F = L ? 24 : 48;
            const float* fm = L ? (f4 + (size_t)b * 1024 * 24 * 24)
                                : (f3 + (size_t)b * 512 * 48 * 48);
            {
                int total = NP * C * 576;
                extract_patches_kernel<<<cdiv(total, 256), 256>>>(fm, patches, C, F, b, L);
            }
            for (int s = 0; s < 3; s++) {
                int total = NP * C * 1024;
                resize_patches_kernel<<<cdiv(total, 256), 256>>>(patches, pf, C, b, L, s);
                sim_kernel<<<NP * F * F, 256>>>(fm, pf, simtmp, C, F, b, L, s);
                sim_resize_kernel<<<cdiv(NP * 2304, 256), 256>>>(simtmp, sims, F, b, L * 3 + s);
            }
        }
    }

    // regressor
    run_conv(sims, rw1, rb1, r1, 6, 6, 48, 48, 196, 7, 1, 3, true);
    upsample_kernel<<<cdiv(6 * 196 * 96 * 96, 256), 256>>>(r1, u1, 6 * 196, 48, 48);
    run_conv(u1, rw2, rb2, r2, 6, 196, 96, 96, 128, 5, 1, 2, true);
    upsample_kernel<<<cdiv(6 * 128 * 192 * 192, 256), 256>>>(r2, u2, 6 * 128, 96, 96);
    run_conv(u2, rw3, rb3, r3, 6, 128, 192, 192, 64, 3, 1, 1, true);
    upsample_kernel<<<cdiv(6 * 64 * 384 * 384, 256), 256>>>(r3, u3, 6 * 64, 192, 192);
    run_conv(u3, rw4, rb4, r4, 6, 64, 384, 384, 32, 1, 1, 0, true);
    run_conv(r4, rw5, rb5, r5, 6, 32, 384, 384, 1, 1, 1, 0, true);

    maxp_kernel<<<cdiv(NB * 384 * 384, 256), 256>>>(r5, out);
}

// round 2
// speedup vs baseline: 1.8012x; 1.8012x over previous
#include <cuda_runtime.h>
#include <math.h>

// ============================================================================
// FamNet pipeline, fp32, shared-memory tiled convolutions.
// ============================================================================

#define NB 2
#define NP 3

// ---------------- device scratch (no allocations allowed) -------------------
__device__ float g_x1[2 * 64 * 192 * 192];
__device__ float g_x2[2 * 256 * 96 * 96];
__device__ float g_f3[2 * 512 * 48 * 48];
__device__ float g_f4[2 * 1024 * 24 * 24];
__device__ float g_patches[3 * 1024 * 24 * 24];   // stride-24 layout
__device__ float g_pf[3 * 1024 * 32 * 32];        // stride-32 layout
__device__ float g_simtmp[3 * 48 * 48];
__device__ float g_sims[2 * 3 * 6 * 48 * 48];
__device__ float g_r1[6 * 196 * 48 * 48];
__device__ float g_u1[6 * 196 * 96 * 96];
__device__ float g_r2[6 * 128 * 96 * 96];
__device__ float g_u2[6 * 128 * 192 * 192];
__device__ float g_r3[6 * 64 * 192 * 192];
__device__ float g_u3[6 * 64 * 384 * 384];
__device__ float g_r4[6 * 32 * 384 * 384];
__device__ float g_r5[6 * 384 * 384];

// ---------------- box / scale metadata (computed on device) -----------------
__device__ int g_tl[2][2][3][2];
__device__ int g_crop[2][2][3][2];
__device__ int g_PH[2][2], g_PW[2][2];
__device__ int g_PHs[2][2][3], g_PWs[2][2][3];

__global__ void meta_kernel(const float* __restrict__ tlbrs) {
    if (threadIdx.x != 0 || blockIdx.x != 0) return;
    const double scales[3] = {1.0, 0.9, 1.1};
    for (int b = 0; b < NB; b++) {
        for (int L = 0; L < 2; L++) {
            int F = (L == 0) ? 48 : 24;
            float inv = (float)F / 384.0f;
            int maxh = 0, maxw = 0;
            for (int p = 0; p < NP; p++) {
                const float* v = tlbrs + (b * NP + p) * 4;
                float sct = v[0] * inv, scl = v[1] * inv;
                float scb = v[2] * inv, scr = v[3] * inv;
                int top = (int)floorf(sct); if (top < 0) top = 0;
                int left = (int)floorf(scl); if (left < 0) left = 0;
                int bot = (int)ceilf(scb) + 1; if (bot > F) bot = F;
                int right = (int)ceilf(scr) + 1; if (right > F) right = F;
                g_tl[b][L][p][0] = top;  g_tl[b][L][p][1] = left;
                g_crop[b][L][p][0] = bot - top;  g_crop[b][L][p][1] = right - left;
                if (bot - top > maxh) maxh = bot - top;
                if (right - left > maxw) maxw = right - left;
            }
            g_PH[b][L] = maxh; g_PW[b][L] = maxw;
            for (int s = 0; s < 3; s++) {
                int ph = (int)ceil((double)maxh * scales[s]);
                int pw = (int)ceil((double)maxw * scales[s]);
                if (ph < 1) ph = maxh;
                if (pw < 1) pw = maxw;
                g_PHs[b][L][s] = ph; g_PWs[b][L][s] = pw;
            }
        }
    }
}

// ---------------- tiled conv: 32x4 spatial x 16 couts per block --------------
// 256 threads: tx(32) x tyg(2) x tcg(4). Each thread: 2 y-rows x 4 couts.
template <int K, int STRIDE>
__global__ void conv_tiled(const float* __restrict__ in, const float* __restrict__ wt,
                           const float* __restrict__ bias, float* __restrict__ out,
                           int N, int Cin, int Hin, int Win,
                           int Cout, int Hout, int Wout, int pad, int relu, int cotiles) {
    constexpr int TX = 32, TY = 4, CO = 16;
    constexpr int IH = (TY - 1) * STRIDE + K;
    constexpr int IW = (TX - 1) * STRIDE + K;

    __shared__ float s_in[IH * IW];
    __shared__ float s_w[CO * K * K];

    const int tx  = threadIdx.x & 31;
    const int tyg = (threadIdx.x >> 5) & 1;
    const int tcg = threadIdx.x >> 6;

    const int bx = blockIdx.x, by = blockIdx.y;
    const int n   = blockIdx.z / cotiles;
    const int co0 = (blockIdx.z % cotiles) * CO;

    const int ix0 = bx * TX * STRIDE - pad;
    const int iy0 = by * TY * STRIDE - pad;

    float acc[2][4] = {};

    const size_t in_n = (size_t)n * Cin * Hin * Win;

    for (int ci = 0; ci < Cin; ci++) {
        __syncthreads();
        // stage input tile
        const float* ip = in + in_n + (size_t)ci * Hin * Win;
        for (int i = threadIdx.x; i < IH * IW; i += 256) {
            int r = i / IW, c = i - r * IW;
            int gy = iy0 + r, gx = ix0 + c;
            float v = 0.0f;
            if ((unsigned)gy < (unsigned)Hin && (unsigned)gx < (unsigned)Win)
                v = __ldg(ip + (size_t)gy * Win + gx);
            s_in[i] = v;
        }
        // stage weights for 16 couts
        for (int i = threadIdx.x; i < CO * K * K; i += 256) {
            int co = co0 + i / (K * K);
            float v = 0.0f;
            if (co < Cout)
                v = __ldg(wt + ((size_t)co * Cin + ci) * (K * K) + (i % (K * K)));
            s_w[i] = v;
        }
        __syncthreads();

#pragma unroll
        for (int kh = 0; kh < K; kh++) {
#pragma unroll
            for (int kw = 0; kw < K; kw++) {
                float w0 = s_w[(tcg * 4 + 0) * K * K + kh * K + kw];
                float w1 = s_w[(tcg * 4 + 1) * K * K + kh * K + kw];
                float w2 = s_w[(tcg * 4 + 2) * K * K + kh * K + kw];
                float w3 = s_w[(tcg * 4 + 3) * K * K + kh * K + kw];
                float i0 = s_in[((2 * tyg + 0) * STRIDE + kh) * IW + tx * STRIDE + kw];
                float i1 = s_in[((2 * tyg + 1) * STRIDE + kh) * IW + tx * STRIDE + kw];
                acc[0][0] = fmaf(i0, w0, acc[0][0]);
                acc[0][1] = fmaf(i0, w1, acc[0][1]);
                acc[0][2] = fmaf(i0, w2, acc[0][2]);
                acc[0][3] = fmaf(i0, w3, acc[0][3]);
                acc[1][0] = fmaf(i1, w0, acc[1][0]);
                acc[1][1] = fmaf(i1, w1, acc[1][1]);
                acc[1][2] = fmaf(i1, w2, acc[1][2]);
                acc[1][3] = fmaf(i1, w3, acc[1][3]);
            }
        }
    }

    const int ox = bx * TX + tx;
    if (ox >= Wout) return;
#pragma unroll
    for (int yy = 0; yy < 2; yy++) {
        int oy = by * TY + 2 * tyg + yy;
        if (oy >= Hout) continue;
#pragma unroll
        for (int c = 0; c < 4; c++) {
            int co = co0 + tcg * 4 + c;
            if (co >= Cout) continue;
            float v = acc[yy][c];
            if (bias) v += __ldg(bias + co);
            if (relu) v = fmaxf(v, 0.0f);
            out[(((size_t)n * Cout + co) * Hout + oy) * Wout + ox] = v;
        }
    }
}

// ---------------- half-pixel bilinear patch extraction ----------------------
__global__ void extract_patches_kernel(const float* __restrict__ fm, float* __restrict__ patches,
                                       int C, int F, int b, int L) {
    int idx = blockIdx.x * blockDim.x + threadIdx.x;
    int total = NP * C * 24 * 24;
    if (idx >= total) return;
    int ox = idx % 24;
    int oy = (idx / 24) % 24;
    int c = (idx / 576) % C;
    int p = idx / (576 * C);
    int PH = g_PH[b][L], PW = g_PW[b][L];
    if (oy >= PH || ox >= PW) return;
    int top = g_tl[b][L][p][0], left = g_tl[b][L][p][1];
    int h = g_crop[b][L][p][0], w = g_crop[b][L][p][1];

    float sy = ((float)oy + 0.5f) * ((float)h / (float)PH) - 0.5f;
    if (sy < 0.0f) sy = 0.0f;
    float sx = ((float)ox + 0.5f) * ((float)w / (float)PW) - 0.5f;
    if (sx < 0.0f) sx = 0.0f;
    int y0 = (int)sy; float ty = sy - (float)y0;
    int x0 = (int)sx; float tx = sx - (float)x0;
    if (y0 > h - 1) { y0 = h - 1; ty = 0.0f; }
    if (x0 > w - 1) { x0 = w - 1; tx = 0.0f; }
    int y1 = min(y0 + 1, h - 1);
    int x1 = min(x0 + 1, w - 1);

    const float* base = fm + ((size_t)c * F + top) * F + left;
    float v00 = base[y0 * F + x0], v01 = base[y0 * F + x1];
    float v10 = base[y1 * F + x0], v11 = base[y1 * F + x1];
    float val = v00 * (1.0f - ty) * (1.0f - tx) + v01 * (1.0f - ty) * tx
              + v10 * ty * (1.0f - tx) + v11 * ty * tx;
    patches[((size_t)(p * C + c) * 24 + oy) * 24 + ox] = val;
}

__global__ void resize_patches_kernel(const float* __restrict__ patches, float* __restrict__ pf,
                                      int C, int b, int L, int s) {
    int idx = blockIdx.x * blockDim.x + threadIdx.x;
    int total = NP * C * 32 * 32;
    if (idx >= total) return;
    int ox = idx % 32;
    int oy = (idx / 32) % 32;
    int c = (idx / 1024) % C;
    int p = idx / (1024 * C);
    int PHs = g_PHs[b][L][s], PWs = g_PWs[b][L][s];
    if (oy >= PHs || ox >= PWs) return;
    int PH = g_PH[b][L], PW = g_PW[b][L];

    float sy = ((float)oy + 0.5f) * ((float)PH / (float)PHs) - 0.5f;
    if (sy < 0.0f) sy = 0.0f;
    float sx = ((float)ox + 0.5f) * ((float)PW / (float)PWs) - 0.5f;
    if (sx < 0.0f) sx = 0.0f;
    int y0 = (int)sy; float ty = sy - (float)y0;
    int x0 = (int)sx; float tx = sx - (float)x0;
    if (y0 > PH - 1) { y0 = PH - 1; ty = 0.0f; }
    if (x0 > PW - 1) { x0 = PW - 1; tx = 0.0f; }
    int y1 = min(y0 + 1, PH - 1);
    int x1 = min(x0 + 1, PW - 1);

    const float* base = patches + (size_t)(p * C + c) * 576;
    float v00 = base[y0 * 24 + x0], v01 = base[y0 * 24 + x1];
    float v10 = base[y1 * 24 + x0], v11 = base[y1 * 24 + x1];
    float val = v00 * (1.0f - ty) * (1.0f - tx) + v01 * (1.0f - ty) * tx
              + v10 * ty * (1.0f - tx) + v11 * ty * tx;
    pf[((size_t)(p * C + c) * 32 + oy) * 32 + ox] = val;
}

// ---------------- correlation: one block per output pixel -------------------
__global__ void sim_kernel(const float* __restrict__ fm, const float* __restrict__ pf,
                           float* __restrict__ simtmp, int C, int F, int b, int L, int s) {
    int blk = blockIdx.x;
    int p = blk / (F * F);
    int rem = blk % (F * F);
    int y = rem / F, x = rem % F;
    int PHs = g_PHs[b][L][s], PWs = g_PWs[b][L][s];
    int padT = PHs >> 1, padL = PWs >> 1;
    int phw = PHs * PWs;
    int tid = threadIdx.x;

    int fmo[3], pfo[3];
#pragma unroll
    for (int k = 0; k < 3; k++) {
        fmo[k] = -1; pfo[k] = 0;
        int ij = tid + k * 256;
        if (ij < phw) {
            int i = ij / PWs, j = ij - i * PWs;
            int iy = y + i - padT, ix = x + j - padL;
            if (iy >= 0 && iy < F && ix >= 0 && ix < F) {
                fmo[k] = iy * F + ix;
                pfo[k] = i * 32 + j;
            }
        }
    }
    float acc0 = 0.0f, acc1 = 0.0f;
    const float* pfb = pf + (size_t)p * C * 1024;
    for (int c = 0; c < C; c += 2) {
        const float* fmc0 = fm + (size_t)c * F * F;
        const float* fmc1 = fmc0 + F * F;
        const float* pfc0 = pfb + (size_t)c * 1024;
        const float* pfc1 = pfc0 + 1024;
#pragma unroll
        for (int k = 0; k < 3; k++) {
            if (fmo[k] >= 0) {
                acc0 = fmaf(__ldg(fmc0 + fmo[k]), pfc0[pfo[k]], acc0);
                acc1 = fmaf(__ldg(fmc1 + fmo[k]), pfc1[pfo[k]], acc1);
            }
        }
    }
    __shared__ float red[256];
    red[tid] = acc0 + acc1;
    __syncthreads();
    for (int off = 128; off > 0; off >>= 1) {
        if (tid < off) red[tid] += red[tid + off];
        __syncthreads();
    }
    if (tid == 0) simtmp[blk] = red[0];
}

__global__ void sim_resize_kernel(const float* __restrict__ simtmp, float* __restrict__ sims,
                                  int F, int b, int ch) {
    int idx = blockIdx.x * blockDim.x + threadIdx.x;
    if (idx >= NP * 48 * 48) return;
    int x = idx % 48;
    int y = (idx / 48) % 48;
    int p = idx / 2304;

    float sy = ((float)y + 0.5f) * ((float)F / 48.0f) - 0.5f;
    if (sy < 0.0f) sy = 0.0f;
    float sx = ((float)x + 0.5f) * ((float)F / 48.0f) - 0.5f;
    if (sx < 0.0f) sx = 0.0f;
    int y0 = (int)sy; float ty = sy - (float)y0;
    int x0 = (int)sx; float tx = sx - (float)x0;
    if (y0 > F - 1) { y0 = F - 1; ty = 0.0f; }
    if (x0 > F - 1) { x0 = F - 1; tx = 0.0f; }
    int y1 = min(y0 + 1, F - 1);
    int x1 = min(x0 + 1, F - 1);

    const float* base = simtmp + (size_t)p * F * F;
    float v00 = base[y0 * F + x0], v01 = base[y0 * F + x1];
    float v10 = base[y1 * F + x0], v11 = base[y1 * F + x1];
    float val = v00 * (1.0f - ty) * (1.0f - tx) + v01 * (1.0f - ty) * tx
              + v10 * ty * (1.0f - tx) + v11 * ty * tx;
    sims[((size_t)(b * NP + p) * 6 + ch) * 2304 + y * 48 + x] = val;
}

// ---------------- align-corners 2x bilinear upsample ------------------------
__global__ void upsample_kernel(const float* __restrict__ in, float* __restrict__ out,
                                int NC, int h, int w) {
    int H = 2 * h, W = 2 * w;
    int idx = blockIdx.x * blockDim.x + threadIdx.x;
    int total = NC * H * W;
    if (idx >= total) return;
    int ox = idx % W;
    int oy = (idx / W) % H;
    int nc = idx / (H * W);

    float stepy = (float)(h - 1) / (float)(H - 1);
    float stepx = (float)(w - 1) / (float)(W - 1);
    float py = (float)oy * stepy;
    float px = (float)ox * stepx;
    int y0 = (int)py; float ty = py - (float)y0;
    int x0 = (int)px; float tx = px - (float)x0;
    if (y0 > h - 1) { y0 = h - 1; ty = 0.0f; }
    if (x0 > w - 1) { x0 = w - 1; tx = 0.0f; }
    int y1 = min(y0 + 1, h - 1);
    int x1 = min(x0 + 1, w - 1);

    const float* ib = in + (size_t)nc * h * w;
    float v00 = ib[y0 * w + x0], v01 = ib[y0 * w + x1];
    float v10 = ib[y1 * w + x0], v11 = ib[y1 * w + x1];
    out[idx] = v00 * (1.0f - ty) * (1.0f - tx) + v01 * (1.0f - ty) * tx
             + v10 * ty * (1.0f - tx) + v11 * ty * tx;
}

// ---------------- final max over P ------------------------------------------
__global__ void maxp_kernel(const float* __restrict__ r5, float* __restrict__ out) {
    int idx = blockIdx.x * blockDim.x + threadIdx.x;
    const int HW = 384 * 384;
    if (idx >= NB * HW) return;
    int b = idx / HW;
    int r = idx % HW;
    float m = r5[(size_t)(b * NP + 0) * HW + r];
    m = fmaxf(m, r5[(size_t)(b * NP + 1) * HW + r]);
    m = fmaxf(m, r5[(size_t)(b * NP + 2) * HW + r]);
    out[idx] = m;
}

// ---------------- host-side launch helpers ----------------------------------
static inline int cdiv(int a, int b) { return (a + b - 1) / b; }

static void run_conv(const float* in, const float* w, const float* b, float* out,
                     int N, int Cin, int Hin, int Win, int Cout,
                     int K, int stride, int pad, bool relu) {
    int Hout = (Hin + 2 * pad - K) / stride + 1;
    int Wout = (Win + 2 * pad - K) / stride + 1;
    int cotiles = cdiv(Cout, 16);
    dim3 grid(cdiv(Wout, 32), cdiv(Hout, 4), N * cotiles);
    int rl = relu ? 1 : 0;
    if (stride == 2) {
        if (K == 7) conv_tiled<7, 2><<<grid, 256>>>(in, w, b, out, N, Cin, Hin, Win, Cout, Hout, Wout, pad, rl, cotiles);
        else        conv_tiled<3, 2><<<grid, 256>>>(in, w, b, out, N, Cin, Hin, Win, Cout, Hout, Wout, pad, rl, cotiles);
    } else {
        if (K == 7)      conv_tiled<7, 1><<<grid, 256>>>(in, w, b, out, N, Cin, Hin, Win, Cout, Hout, Wout, pad, rl, cotiles);
        else if (K == 5) conv_tiled<5, 1><<<grid, 256>>>(in, w, b, out, N, Cin, Hin, Win, Cout, Hout, Wout, pad, rl, cotiles);
        else if (K == 3) conv_tiled<3, 1><<<grid, 256>>>(in, w, b, out, N, Cin, Hin, Win, Cout, Hout, Wout, pad, rl, cotiles);
        else             conv_tiled<1, 1><<<grid, 256>>>(in, w, b, out, N, Cin, Hin, Win, Cout, Hout, Wout, pad, rl, cotiles);
    }
}

extern "C" void kernel_launch(void* const* d_in, const int* in_sizes, int n_in,
                              void* d_out, int out_size) {
    const float* images = (const float*)d_in[0];
    const float* tlbrs  = (const float*)d_in[1];
    const float* fw1 = (const float*)d_in[2];
    const float* fw2 = (const float*)d_in[3];
    const float* fw3 = (const float*)d_in[4];
    const float* fw4 = (const float*)d_in[5];
    const float* rw1 = (const float*)d_in[6];
    const float* rb1 = (const float*)d_in[7];
    const float* rw2 = (const float*)d_in[8];
    const float* rb2 = (const float*)d_in[9];
    const float* rw3 = (const float*)d_in[10];
    const float* rb3 = (const float*)d_in[11];
    const float* rw4 = (const float*)d_in[12];
    const float* rb4 = (const float*)d_in[13];
    const float* rw5 = (const float*)d_in[14];
    const float* rb5 = (const float*)d_in[15];
    float* out = (float*)d_out;

    float *x1, *x2, *f3, *f4, *patches, *pf, *simtmp, *sims;
    float *r1, *u1, *r2, *u2, *r3, *u3, *r4, *r5;
    cudaGetSymbolAddress((void**)&x1, g_x1);
    cudaGetSymbolAddress((void**)&x2, g_x2);
    cudaGetSymbolAddress((void**)&f3, g_f3);
    cudaGetSymbolAddress((void**)&f4, g_f4);
    cudaGetSymbolAddress((void**)&patches, g_patches);
    cudaGetSymbolAddress((void**)&pf, g_pf);
    cudaGetSymbolAddress((void**)&simtmp, g_simtmp);
    cudaGetSymbolAddress((void**)&sims, g_sims);
    cudaGetSymbolAddress((void**)&r1, g_r1);
    cudaGetSymbolAddress((void**)&u1, g_u1);
    cudaGetSymbolAddress((void**)&r2, g_r2);
    cudaGetSymbolAddress((void**)&u2, g_u2);
    cudaGetSymbolAddress((void**)&r3, g_r3);
    cudaGetSymbolAddress((void**)&u3, g_u3);
    cudaGetSymbolAddress((void**)&r4, g_r4);
    cudaGetSymbolAddress((void**)&r5, g_r5);

    // box metadata
    meta_kernel<<<1, 1>>>(tlbrs);

    // backbone
    run_conv(images, fw1, nullptr, x1, 2, 3, 384, 384, 64, 7, 2, 3, true);
    run_conv(x1, fw2, nullptr, x2, 2, 64, 192, 192, 256, 3, 2, 1, true);
    run_conv(x2, fw3, nullptr, f3, 2, 256, 96, 96, 512, 3, 2, 1, true);
    run_conv(f3, fw4, nullptr, f4, 2, 512, 48, 48, 1024, 3, 2, 1, true);

    // similarity features
    for (int b = 0; b < NB; b++) {
        for (int L = 0; L < 2; L++) {
            int C = L ? 1024 : 512;
            int F = L ? 24 : 48;
            const float* fm = L ? (f4 + (size_t)b * 1024 * 24 * 24)
                                : (f3 + (size_t)b * 512 * 48 * 48);
            {
                int total = NP * C * 576;
                extract_patches_kernel<<<cdiv(total, 256), 256>>>(fm, patches, C, F, b, L);
            }
            for (int s = 0; s < 3; s++) {
                int total = NP * C * 1024;
                resize_patches_kernel<<<cdiv(total, 256), 256>>>(patches, pf, C, b, L, s);
                sim_kernel<<<NP * F * F, 256>>>(fm, pf, simtmp, C, F, b, L, s);
                sim_resize_kernel<<<cdiv(NP * 2304, 256), 256>>>(simtmp, sims, F, b, L * 3 + s);
            }
        }
    }

    // regressor
    run_conv(sims, rw1, rb1, r1, 6, 6, 48, 48, 196, 7, 1, 3, true);
    upsample_kernel<<<cdiv(6 * 196 * 96 * 96, 256), 256>>>(r1, u1, 6 * 196, 48, 48);
    run_conv(u1, rw2, rb2, r2, 6, 196, 96, 96, 128, 5, 1, 2, true);
    upsample_kernel<<<cdiv(6 * 128 * 192 * 192, 256), 256>>>(r2, u2, 6 * 128, 96, 96);
    run_conv(u2, rw3, rb3, r3, 6, 128, 192, 192, 64, 3, 1, 1, true);
    upsample_kernel<<<cdiv(6 * 64 * 384 * 384, 256), 256>>>(r3, u3, 6 * 64, 192, 192);
    run_conv(u3, rw4, rb4, r4, 6, 64, 384, 384, 32, 1, 1, 0, true);
    run_conv(r4, rw5, rb5, r5, 6, 32, 384, 384, 1, 1, 1, 0, true);

    maxp_kernel<<<cdiv(NB * 384 * 384, 256), 256>>>(r5, out);
}

// round 3
// speedup vs baseline: 3.3219x; 1.8443x over previous
#include <cuda_runtime.h>
#include <math.h>

// ============================================================================
// FamNet pipeline, fp32, register-tiled convolutions (16 outputs/thread).
// ============================================================================

#define NB 2
#define NP 3

// ---------------- device scratch (no allocations allowed) -------------------
__device__ float g_x1[2 * 64 * 192 * 192];
__device__ float g_x2[2 * 256 * 96 * 96];
__device__ float g_f3[2 * 512 * 48 * 48];
__device__ float g_f4[2 * 1024 * 24 * 24];
__device__ float g_patches[3 * 1024 * 24 * 24];   // stride-24 layout
__device__ float g_pf[3 * 1024 * 32 * 32];        // stride-32 layout
__device__ float g_simtmp[3 * 48 * 48];
__device__ float g_sims[2 * 3 * 6 * 48 * 48];
__device__ float g_r1[6 * 196 * 48 * 48];
__device__ float g_u1[6 * 196 * 96 * 96];
__device__ float g_r2[6 * 128 * 96 * 96];
__device__ float g_u2[6 * 128 * 192 * 192];
__device__ float g_r3[6 * 64 * 192 * 192];
__device__ float g_u3[6 * 64 * 384 * 384];
__device__ float g_r4[6 * 32 * 384 * 384];
__device__ float g_wbuf[1024 * 512 * 9];          // transposed weights [ci][k][co_pad]

// ---------------- box / scale metadata (computed on device) -----------------
__device__ int g_tl[2][2][3][2];
__device__ int g_crop[2][2][3][2];
__device__ int g_PH[2][2], g_PW[2][2];
__device__ int g_PHs[2][2][3], g_PWs[2][2][3];

__global__ void meta_kernel(const float* __restrict__ tlbrs) {
    if (threadIdx.x != 0 || blockIdx.x != 0) return;
    const double scales[3] = {1.0, 0.9, 1.1};
    for (int b = 0; b < NB; b++) {
        for (int L = 0; L < 2; L++) {
            int F = (L == 0) ? 48 : 24;
            float inv = (float)F / 384.0f;
            int maxh = 0, maxw = 0;
            for (int p = 0; p < NP; p++) {
                const float* v = tlbrs + (b * NP + p) * 4;
                float sct = v[0] * inv, scl = v[1] * inv;
                float scb = v[2] * inv, scr = v[3] * inv;
                int top = (int)floorf(sct); if (top < 0) top = 0;
                int left = (int)floorf(scl); if (left < 0) left = 0;
                int bot = (int)ceilf(scb) + 1; if (bot > F) bot = F;
                int right = (int)ceilf(scr) + 1; if (right > F) right = F;
                g_tl[b][L][p][0] = top;  g_tl[b][L][p][1] = left;
                g_crop[b][L][p][0] = bot - top;  g_crop[b][L][p][1] = right - left;
                if (bot - top > maxh) maxh = bot - top;
                if (right - left > maxw) maxw = right - left;
            }
            g_PH[b][L] = maxh; g_PW[b][L] = maxw;
            for (int s = 0; s < 3; s++) {
                int ph = (int)ceil((double)maxh * scales[s]);
                int pw = (int)ceil((double)maxw * scales[s]);
                if (ph < 1) ph = maxh;
                if (pw < 1) pw = maxw;
                g_PHs[b][L][s] = ph; g_PWs[b][L][s] = pw;
            }
        }
    }
}

// ---------------- weight transpose: [co][ci][k] -> [ci][k][co_pad] ----------
__global__ void wtrans_kernel(const float* __restrict__ wt, float* __restrict__ wbuf,
                              int Cin, int Cout, int Co_pad, int K2, int total) {
    int idx = blockIdx.x * blockDim.x + threadIdx.x;
    if (idx >= total) return;
    int co = idx % Co_pad;
    int t = idx / Co_pad;
    int kk = t % K2;
    int ci = t / K2;
    wbuf[idx] = (co < Cout) ? __ldg(wt + ((size_t)co * Cin + ci) * K2 + kk) : 0.0f;
}

// ---------------- tiled conv: 32x(x) 4(y) spatial x 32 couts per block -------
// 256 threads: tx(16) x ty(2) x tc(8). Thread computes 2x * 2y * 4co.
template <int K, int STRIDE>
__global__ void conv_tiled2(const float* __restrict__ in, const float* __restrict__ wbuf,
                            const float* __restrict__ bias, float* __restrict__ out,
                            int N, int Cin, int Hin, int Win,
                            int Cout, int Co_pad, int Hout, int Wout,
                            int pad, int relu, int cotiles) {
    constexpr int K2 = K * K;
    constexpr int IH = 3 * STRIDE + K;
    constexpr int IW = 31 * STRIDE + K;

    __shared__ float s_in[IH * IW];
    __shared__ float4 s_w[K2 * 8];

    const int tid = threadIdx.x;
    const int tx = tid & 15;
    const int ty = (tid >> 4) & 1;
    const int tc = tid >> 5;

    const int bx = blockIdx.x, by = blockIdx.y;
    const int n   = blockIdx.z / cotiles;
    const int co0 = (blockIdx.z % cotiles) * 32;

    const int ix0 = bx * 32 * STRIDE - pad;
    const int iy0 = by * 4 * STRIDE - pad;

    float acc[2][2][4] = {};
    const size_t in_n = (size_t)n * Cin * Hin * Win;

    for (int ci = 0; ci < Cin; ci++) {
        __syncthreads();
        const float* ip = in + in_n + (size_t)ci * Hin * Win;
#pragma unroll 2
        for (int i = tid; i < IH * IW; i += 256) {
            int r = i / IW, c = i - r * IW;
            int gy = iy0 + r, gx = ix0 + c;
            float v = 0.0f;
            if ((unsigned)gy < (unsigned)Hin && (unsigned)gx < (unsigned)Win)
                v = __ldg(ip + (size_t)gy * Win + gx);
            s_in[i] = v;
        }
        const float* wp = wbuf + (size_t)ci * K2 * Co_pad + co0;
#pragma unroll 2
        for (int i = tid; i < K2 * 32; i += 256) {
            int kk = i >> 5, c = i & 31;
            ((float*)s_w)[i] = __ldg(wp + kk * Co_pad + c);
        }
        __syncthreads();

#pragma unroll
        for (int kh = 0; kh < K; kh++) {
#pragma unroll
            for (int kw = 0; kw < K; kw++) {
                float4 w = s_w[(kh * K + kw) * 8 + tc];
                float iv[2][2];
#pragma unroll
                for (int yy = 0; yy < 2; yy++)
#pragma unroll
                    for (int xx = 0; xx < 2; xx++)
                        iv[yy][xx] = s_in[((2 * ty + yy) * STRIDE + kh) * IW
                                          + (2 * tx + xx) * STRIDE + kw];
#pragma unroll
                for (int yy = 0; yy < 2; yy++)
#pragma unroll
                    for (int xx = 0; xx < 2; xx++) {
                        acc[yy][xx][0] = fmaf(iv[yy][xx], w.x, acc[yy][xx][0]);
                        acc[yy][xx][1] = fmaf(iv[yy][xx], w.y, acc[yy][xx][1]);
                        acc[yy][xx][2] = fmaf(iv[yy][xx], w.z, acc[yy][xx][2]);
                        acc[yy][xx][3] = fmaf(iv[yy][xx], w.w, acc[yy][xx][3]);
                    }
            }
        }
    }

    const int ox = bx * 32 + 2 * tx;
    if (ox >= Wout) return;
#pragma unroll
    for (int c = 0; c < 4; c++) {
        int co = co0 + tc * 4 + c;
        if (co >= Cout) continue;
        float bv = bias ? __ldg(bias + co) : 0.0f;
#pragma unroll
        for (int yy = 0; yy < 2; yy++) {
            int oy = by * 4 + 2 * ty + yy;
            if (oy >= Hout) continue;
            float v0 = acc[yy][0][c] + bv;
            float v1 = acc[yy][1][c] + bv;
            if (relu) { v0 = fmaxf(v0, 0.0f); v1 = fmaxf(v1, 0.0f); }
            float2* o = (float2*)(out + (((size_t)n * Cout + co) * Hout + oy) * Wout + ox);
            *o = make_float2(v0, v1);
        }
    }
}

// ---------------- half-pixel bilinear patch extraction ----------------------
__global__ void extract_patches_kernel(const float* __restrict__ fm, float* __restrict__ patches,
                                       int C, int F, int b, int L) {
    int idx = blockIdx.x * blockDim.x + threadIdx.x;
    int total = NP * C * 24 * 24;
    if (idx >= total) return;
    int ox = idx % 24;
    int oy = (idx / 24) % 24;
    int c = (idx / 576) % C;
    int p = idx / (576 * C);
    int PH = g_PH[b][L], PW = g_PW[b][L];
    if (oy >= PH || ox >= PW) return;
    int top = g_tl[b][L][p][0], left = g_tl[b][L][p][1];
    int h = g_crop[b][L][p][0], w = g_crop[b][L][p][1];

    float sy = ((float)oy + 0.5f) * ((float)h / (float)PH) - 0.5f;
    if (sy < 0.0f) sy = 0.0f;
    float sx = ((float)ox + 0.5f) * ((float)w / (float)PW) - 0.5f;
    if (sx < 0.0f) sx = 0.0f;
    int y0 = (int)sy; float ty = sy - (float)y0;
    int x0 = (int)sx; float tx = sx - (float)x0;
    if (y0 > h - 1) { y0 = h - 1; ty = 0.0f; }
    if (x0 > w - 1) { x0 = w - 1; tx = 0.0f; }
    int y1 = min(y0 + 1, h - 1);
    int x1 = min(x0 + 1, w - 1);

    const float* base = fm + ((size_t)c * F + top) * F + left;
    float v00 = base[y0 * F + x0], v01 = base[y0 * F + x1];
    float v10 = base[y1 * F + x0], v11 = base[y1 * F + x1];
    float val = v00 * (1.0f - ty) * (1.0f - tx) + v01 * (1.0f - ty) * tx
              + v10 * ty * (1.0f - tx) + v11 * ty * tx;
    patches[((size_t)(p * C + c) * 24 + oy) * 24 + ox] = val;
}

__global__ void resize_patches_kernel(const float* __restrict__ patches, float* __restrict__ pf,
                                      int C, int b, int L, int s) {
    int idx = blockIdx.x * blockDim.x + threadIdx.x;
    int total = NP * C * 32 * 32;
    if (idx >= total) return;
    int ox = idx % 32;
    int oy = (idx / 32) % 32;
    int c = (idx / 1024) % C;
    int p = idx / (1024 * C);
    int PHs = g_PHs[b][L][s], PWs = g_PWs[b][L][s];
    if (oy >= PHs || ox >= PWs) return;
    int PH = g_PH[b][L], PW = g_PW[b][L];

    float sy = ((float)oy + 0.5f) * ((float)PH / (float)PHs) - 0.5f;
    if (sy < 0.0f) sy = 0.0f;
    float sx = ((float)ox + 0.5f) * ((float)PW / (float)PWs) - 0.5f;
    if (sx < 0.0f) sx = 0.0f;
    int y0 = (int)sy; float ty = sy - (float)y0;
    int x0 = (int)sx; float tx = sx - (float)x0;
    if (y0 > PH - 1) { y0 = PH - 1; ty = 0.0f; }
    if (x0 > PW - 1) { x0 = PW - 1; tx = 0.0f; }
    int y1 = min(y0 + 1, PH - 1);
    int x1 = min(x0 + 1, PW - 1);

    const float* base = patches + (size_t)(p * C + c) * 576;
    float v00 = base[y0 * 24 + x0], v01 = base[y0 * 24 + x1];
    float v10 = base[y1 * 24 + x0], v11 = base[y1 * 24 + x1];
    float val = v00 * (1.0f - ty) * (1.0f - tx) + v01 * (1.0f - ty) * tx
              + v10 * ty * (1.0f - tx) + v11 * ty * tx;
    pf[((size_t)(p * C + c) * 32 + oy) * 32 + ox] = val;
}

// ---------------- correlation: one block per output pixel -------------------
// phw = PHs*PWs <= 256 guaranteed (boxes <= 96px -> PHs,PWs <= 16).
__global__ void sim_kernel(const float* __restrict__ fm, const float* __restrict__ pf,
                           float* __restrict__ simtmp, int C, int F, int b, int L, int s) {
    int blk = blockIdx.x;
    int p = blk / (F * F);
    int rem = blk % (F * F);
    int y = rem / F, x = rem % F;
    int PHs = g_PHs[b][L][s], PWs = g_PWs[b][L][s];
    int padT = PHs >> 1, padL = PWs >> 1;
    int phw = PHs * PWs;
    int tid = threadIdx.x;

    int fmo = -1, pfo = 0;
    if (tid < phw) {
        int i = tid / PWs, j = tid - i * PWs;
        int iy = y + i - padT, ix = x + j - padL;
        if (iy >= 0 && iy < F && ix >= 0 && ix < F) {
            fmo = iy * F + ix;
            pfo = i * 32 + j;
        }
    }
    float a0 = 0.0f, a1 = 0.0f, a2 = 0.0f, a3 = 0.0f;
    if (fmo >= 0) {
        const int FF = F * F;
        const float* fmb = fm + fmo;
        const float* pfb = pf + (size_t)p * C * 1024 + pfo;
        for (int c = 0; c < C; c += 4) {
            a0 = fmaf(__ldg(fmb + (size_t)(c + 0) * FF), __ldg(pfb + ((c + 0) << 10)), a0);
            a1 = fmaf(__ldg(fmb + (size_t)(c + 1) * FF), __ldg(pfb + ((c + 1) << 10)), a1);
            a2 = fmaf(__ldg(fmb + (size_t)(c + 2) * FF), __ldg(pfb + ((c + 2) << 10)), a2);
            a3 = fmaf(__ldg(fmb + (size_t)(c + 3) * FF), __ldg(pfb + ((c + 3) << 10)), a3);
        }
    }
    __shared__ float red[256];
    red[tid] = (a0 + a1) + (a2 + a3);
    __syncthreads();
    for (int off = 128; off > 0; off >>= 1) {
        if (tid < off) red[tid] += red[tid + off];
        __syncthreads();
    }
    if (tid == 0) simtmp[blk] = red[0];
}

__global__ void sim_resize_kernel(const float* __restrict__ simtmp, float* __restrict__ sims,
                                  int F, int b, int ch) {
    int idx = blockIdx.x * blockDim.x + threadIdx.x;
    if (idx >= NP * 48 * 48) return;
    int x = idx % 48;
    int y = (idx / 48) % 48;
    int p = idx / 2304;

    float sy = ((float)y + 0.5f) * ((float)F / 48.0f) - 0.5f;
    if (sy < 0.0f) sy = 0.0f;
    float sx = ((float)x + 0.5f) * ((float)F / 48.0f) - 0.5f;
    if (sx < 0.0f) sx = 0.0f;
    int y0 = (int)sy; float ty = sy - (float)y0;
    int x0 = (int)sx; float tx = sx - (float)x0;
    if (y0 > F - 1) { y0 = F - 1; ty = 0.0f; }
    if (x0 > F - 1) { x0 = F - 1; tx = 0.0f; }
    int y1 = min(y0 + 1, F - 1);
    int x1 = min(x0 + 1, F - 1);

    const float* base = simtmp + (size_t)p * F * F;
    float v00 = base[y0 * F + x0], v01 = base[y0 * F + x1];
    float v10 = base[y1 * F + x0], v11 = base[y1 * F + x1];
    float val = v00 * (1.0f - ty) * (1.0f - tx) + v01 * (1.0f - ty) * tx
              + v10 * ty * (1.0f - tx) + v11 * ty * tx;
    sims[((size_t)(b * NP + p) * 6 + ch) * 2304 + y * 48 + x] = val;
}

// ---------------- align-corners 2x bilinear upsample ------------------------
__global__ void upsample_kernel(const float* __restrict__ in, float* __restrict__ out,
                                int NC, int h, int w) {
    int H = 2 * h, W = 2 * w;
    int idx = blockIdx.x * blockDim.x + threadIdx.x;
    int total = NC * H * W;
    if (idx >= total) return;
    int ox = idx % W;
    int oy = (idx / W) % H;
    int nc = idx / (H * W);

    float stepy = (float)(h - 1) / (float)(H - 1);
    float stepx = (float)(w - 1) / (float)(W - 1);
    float py = (float)oy * stepy;
    float px = (float)ox * stepx;
    int y0 = (int)py; float ty = py - (float)y0;
    int x0 = (int)px; float tx = px - (float)x0;
    if (y0 > h - 1) { y0 = h - 1; ty = 0.0f; }
    if (x0 > w - 1) { x0 = w - 1; tx = 0.0f; }
    int y1 = min(y0 + 1, h - 1);
    int x1 = min(x0 + 1, w - 1);

    const float* ib = in + (size_t)nc * h * w;
    float v00 = ib[y0 * w + x0], v01 = ib[y0 * w + x1];
    float v10 = ib[y1 * w + x0], v11 = ib[y1 * w + x1];
    out[idx] = v00 * (1.0f - ty) * (1.0f - tx) + v01 * (1.0f - ty) * tx
             + v10 * ty * (1.0f - tx) + v11 * ty * tx;
}

// ---------------- fused rw5 (1x1, 32->1) + relu + max over P ----------------
__global__ void tail_kernel(const float* __restrict__ r4, const float* __restrict__ w5,
                            const float* __restrict__ b5, float* __restrict__ out) {
    __shared__ float sw[32];
    if (threadIdx.x < 32) sw[threadIdx.x] = __ldg(w5 + threadIdx.x);
    __syncthreads();
    const int HW = 384 * 384;
    int idx = blockIdx.x * blockDim.x + threadIdx.x;
    if (idx >= NB * HW) return;
    int b = idx / HW;
    int r = idx % HW;
    float bv = __ldg(b5);
    float m = -1e30f;
#pragma unroll
    for (int p = 0; p < NP; p++) {
        const float* base = r4 + ((size_t)(b * NP + p) * 32) * HW + r;
        float s = bv;
#pragma unroll
        for (int c = 0; c < 32; c++)
            s = fmaf(__ldg(base + (size_t)c * HW), sw[c], s);
        s = fmaxf(s, 0.0f);
        m = fmaxf(m, s);
    }
    out[idx] = m;
}

// ---------------- host-side launch helpers ----------------------------------
static inline int cdiv(int a, int b) { return (a + b - 1) / b; }

static float* s_wbuf = nullptr;

static void run_conv(const float* in, const float* w, const float* b, float* out,
                     int N, int Cin, int Hin, int Win, int Cout,
                     int K, int stride, int pad, bool relu) {
    int Hout = (Hin + 2 * pad - K) / stride + 1;
    int Wout = (Win + 2 * pad - K) / stride + 1;
    int cotiles = cdiv(Cout, 32);
    int Co_pad = cotiles * 32;
    int K2 = K * K;

    int wtotal = Cin * K2 * Co_pad;
    wtrans_kernel<<<cdiv(wtotal, 256), 256>>>(w, s_wbuf, Cin, Cout, Co_pad, K2, wtotal);

    dim3 grid(cdiv(Wout, 32), cdiv(Hout, 4), N * cotiles);
    int rl = relu ? 1 : 0;
    if (stride == 2) {
        if (K == 7) conv_tiled2<7, 2><<<grid, 256>>>(in, s_wbuf, b, out, N, Cin, Hin, Win, Cout, Co_pad, Hout, Wout, pad, rl, cotiles);
        else        conv_tiled2<3, 2><<<grid, 256>>>(in, s_wbuf, b, out, N, Cin, Hin, Win, Cout, Co_pad, Hout, Wout, pad, rl, cotiles);
    } else {
        if (K == 7)      conv_tiled2<7, 1><<<grid, 256>>>(in, s_wbuf, b, out, N, Cin, Hin, Win, Cout, Co_pad, Hout, Wout, pad, rl, cotiles);
        else if (K == 5) conv_tiled2<5, 1><<<grid, 256>>>(in, s_wbuf, b, out, N, Cin, Hin, Win, Cout, Co_pad, Hout, Wout, pad, rl, cotiles);
        else if (K == 3) conv_tiled2<3, 1><<<grid, 256>>>(in, s_wbuf, b, out, N, Cin, Hin, Win, Cout, Co_pad, Hout, Wout, pad, rl, cotiles);
        else             conv_tiled2<1, 1><<<grid, 256>>>(in, s_wbuf, b, out, N, Cin, Hin, Win, Cout, Co_pad, Hout, Wout, pad, rl, cotiles);
    }
}

extern "C" void kernel_launch(void* const* d_in, const int* in_sizes, int n_in,
                              void* d_out, int out_size) {
    const float* images = (const float*)d_in[0];
    const float* tlbrs  = (const float*)d_in[1];
    const float* fw1 = (const float*)d_in[2];
    const float* fw2 = (const float*)d_in[3];
    const float* fw3 = (const float*)d_in[4];
    const float* fw4 = (const float*)d_in[5];
    const float* rw1 = (const float*)d_in[6];
    const float* rb1 = (const float*)d_in[7];
    const float* rw2 = (const float*)d_in[8];
    const float* rb2 = (const float*)d_in[9];
    const float* rw3 = (const float*)d_in[10];
    const float* rb3 = (const float*)d_in[11];
    const float* rw4 = (const float*)d_in[12];
    const float* rb4 = (const float*)d_in[13];
    const float* rw5 = (const float*)d_in[14];
    const float* rb5 = (const float*)d_in[15];
    float* out = (float*)d_out;

    float *x1, *x2, *f3, *f4, *patches, *pf, *simtmp, *sims;
    float *r1, *u1, *r2, *u2, *r3, *u3, *r4;
    cudaGetSymbolAddress((void**)&x1, g_x1);
    cudaGetSymbolAddress((void**)&x2, g_x2);
    cudaGetSymbolAddress((void**)&f3, g_f3);
    cudaGetSymbolAddress((void**)&f4, g_f4);
    cudaGetSymbolAddress((void**)&patches, g_patches);
    cudaGetSymbolAddress((void**)&pf, g_pf);
    cudaGetSymbolAddress((void**)&simtmp, g_simtmp);
    cudaGetSymbolAddress((void**)&sims, g_sims);
    cudaGetSymbolAddress((void**)&r1, g_r1);
    cudaGetSymbolAddress((void**)&u1, g_u1);
    cudaGetSymbolAddress((void**)&r2, g_r2);
    cudaGetSymbolAddress((void**)&u2, g_u2);
    cudaGetSymbolAddress((void**)&r3, g_r3);
    cudaGetSymbolAddress((void**)&u3, g_u3);
    cudaGetSymbolAddress((void**)&r4, g_r4);
    cudaGetSymbolAddress((void**)&s_wbuf, g_wbuf);

    // box metadata
    meta_kernel<<<1, 1>>>(tlbrs);

    // backbone
    run_conv(images, fw1, nullptr, x1, 2, 3, 384, 384, 64, 7, 2, 3, true);
    run_conv(x1, fw2, nullptr, x2, 2, 64, 192, 192, 256, 3, 2, 1, true);
    run_conv(x2, fw3, nullptr, f3, 2, 256, 96, 96, 512, 3, 2, 1, true);
    run_conv(f3, fw4, nullptr, f4, 2, 512, 48, 48, 1024, 3, 2, 1, true);

    // similarity features
    for (int b = 0; b < NB; b++) {
        for (int L = 0; L < 2; L++) {
            int C = L ? 1024 : 512;
            int F = L ? 24 : 48;
            const float* fm = L ? (f4 + (size_t)b * 1024 * 24 * 24)
                                : (f3 + (size_t)b * 512 * 48 * 48);
            {
                int total = NP * C * 576;
                extract_patches_kernel<<<cdiv(total, 256), 256>>>(fm, patches, C, F, b, L);
            }
            for (int s = 0; s < 3; s++) {
                int total = NP * C * 1024;
                resize_patches_kernel<<<cdiv(total, 256), 256>>>(patches, pf, C, b, L, s);
                sim_kernel<<<NP * F * F, 256>>>(fm, pf, simtmp, C, F, b, L, s);
                sim_resize_kernel<<<cdiv(NP * 2304, 256), 256>>>(simtmp, sims, F, b, L * 3 + s);
            }
        }
    }

    // regressor
    run_conv(sims, rw1, rb1, r1, 6, 6, 48, 48, 196, 7, 1, 3, true);
    upsample_kernel<<<cdiv(6 * 196 * 96 * 96, 256), 256>>>(r1, u1, 6 * 196, 48, 48);
    run_conv(u1, rw2, rb2, r2, 6, 196, 96, 96, 128, 5, 1, 2, true);
    upsample_kernel<<<cdiv(6 * 128 * 192 * 192, 256), 256>>>(r2, u2, 6 * 128, 96, 96);
    run_conv(u2, rw3, rb3, r3, 6, 128, 192, 192, 64, 3, 1, 1, true);
    upsample_kernel<<<cdiv(6 * 64 * 384 * 384, 256), 256>>>(r3, u3, 6 * 64, 192, 192);
    run_conv(u3, rw4, rb4, r4, 6, 64, 384, 384, 32, 1, 1, 0, true);

    tail_kernel<<<cdiv(NB * 384 * 384, 256), 256>>>(r4, rw5, rb5, out);
}